// round 7
// baseline (speedup 1.0000x reference)
#include <cuda_runtime.h>
#include <cuda_bf16.h>
#include <cstdint>

#define EMBED 2048
#define HD    128
#define NB    4
#define SEQ   2048

// ---------------------------------------------------------------------------
// Scratch globals (bf16 hi/lo split operands)
// ---------------------------------------------------------------------------
__device__ __align__(16) __nv_bfloat16 g_Whi[3 * HD * EMBED];   // [wsel][n][k]
__device__ __align__(16) __nv_bfloat16 g_Wlo[3 * HD * EMBED];
__device__ __align__(16) __nv_bfloat16 g_xhi[(size_t)NB * SEQ * EMBED]; // [row][k]
__device__ __align__(16) __nv_bfloat16 g_xlo[(size_t)NB * SEQ * EMBED];
__device__ __align__(16) __nv_bfloat16 g_qhi[NB * SEQ * HD];    // [b][s][d]
__device__ __align__(16) __nv_bfloat16 g_qlo[NB * SEQ * HD];
__device__ __align__(16) __nv_bfloat16 g_khi[NB * SEQ * HD];    // [b][s][d]
__device__ __align__(16) __nv_bfloat16 g_klo[NB * SEQ * HD];
__device__ __align__(16) __nv_bfloat16 g_vthi[NB * HD * SEQ];   // [b][d][s]
__device__ __align__(16) __nv_bfloat16 g_vtlo[NB * HD * SEQ];

__device__ __forceinline__ uint32_t pk2(__nv_bfloat16 a, __nv_bfloat16 b) {
    return ((uint32_t)__bfloat16_as_ushort(b) << 16) | __bfloat16_as_ushort(a);
}
__device__ __forceinline__ uint32_t smem_u32(const void* p) {
    uint32_t a;
    asm("{ .reg .u64 t; cvta.to.shared.u64 t, %1; cvt.u32.u64 %0, t; }"
        : "=r"(a) : "l"(p));
    return a;
}
__device__ __forceinline__ void mma16816(float* c, const uint32_t* a,
                                         const uint32_t* b) {
    asm volatile(
        "mma.sync.aligned.m16n8k16.row.col.f32.bf16.bf16.f32 "
        "{%0,%1,%2,%3}, {%4,%5,%6,%7}, {%8,%9}, {%0,%1,%2,%3};"
        : "+f"(c[0]), "+f"(c[1]), "+f"(c[2]), "+f"(c[3])
        : "r"(a[0]), "r"(a[1]), "r"(a[2]), "r"(a[3]), "r"(b[0]), "r"(b[1]));
}
__device__ __forceinline__ void ldsm4(uint32_t* r, uint32_t saddr) {
    asm volatile("ldmatrix.sync.aligned.m8n8.x4.shared.b16 {%0,%1,%2,%3}, [%4];"
                 : "=r"(r[0]), "=r"(r[1]), "=r"(r[2]), "=r"(r[3]) : "r"(saddr));
}
__device__ __forceinline__ void cpa16(uint32_t dst, const void* src) {
    asm volatile("cp.async.cg.shared.global [%0], [%1], 16;"
                 :: "r"(dst), "l"(__cvta_generic_to_global(src)) : "memory");
}
#define CP_COMMIT() asm volatile("cp.async.commit_group;" ::: "memory")
#define CP_WAIT1()  asm volatile("cp.async.wait_group 1;" ::: "memory")

// ---------------------------------------------------------------------------
// prep_all: blocks 0..47  -> W fp32 -> K-major bf16 hi/lo
//           blocks 48..271 -> X fp32 -> bf16 hi/lo (row-major, same layout)
// ---------------------------------------------------------------------------
__global__ __launch_bounds__(256)
void prep_all(const float* __restrict__ X,
              const float* __restrict__ Wq, const float* __restrict__ Wk,
              const float* __restrict__ Wv)
{
    __shared__ float Ws[128][132];
    const int t = threadIdx.x;

    if (blockIdx.x < 48) {
        const int w  = blockIdx.x >> 4;
        const int k0 = (blockIdx.x & 15) * 128;
        const float* __restrict__ W = (w == 0) ? Wq : (w == 1 ? Wk : Wv);

        for (int l = 0; l < 64; ++l) {
            int idx = t + l * 256;
            int kk = idx >> 7, n = idx & 127;
            Ws[kk][n] = W[(size_t)(k0 + kk) * HD + n];
        }
        __syncthreads();

        const int n = t >> 1, kh = (t & 1) * 64;
        size_t base = (size_t)w * HD * EMBED + (size_t)n * EMBED + k0 + kh;
        #pragma unroll
        for (int g = 0; g < 8; ++g) {
            uint32_t hp[4], lp[4];
            #pragma unroll
            for (int q = 0; q < 4; ++q) {
                float x0 = Ws[kh + g * 8 + q * 2][n];
                float x1 = Ws[kh + g * 8 + q * 2 + 1][n];
                __nv_bfloat16 h0 = __float2bfloat16(x0);
                __nv_bfloat16 h1 = __float2bfloat16(x1);
                hp[q] = pk2(h0, h1);
                lp[q] = pk2(__float2bfloat16(x0 - __bfloat162float(h0)),
                            __float2bfloat16(x1 - __bfloat162float(h1)));
            }
            *(uint4*)(g_Whi + base + g * 8) = make_uint4(hp[0], hp[1], hp[2], hp[3]);
            *(uint4*)(g_Wlo + base + g * 8) = make_uint4(lp[0], lp[1], lp[2], lp[3]);
        }
    } else {
        // X conversion: 16.8M elements as float4 chunks
        const size_t N4 = (size_t)NB * SEQ * EMBED / 4;      // 4,194,304
        const size_t nthr = 224 * 256;
        size_t c = (size_t)(blockIdx.x - 48) * 256 + t;
        for (; c < N4; c += nthr) {
            float4 v = *(const float4*)(X + c * 4);
            __nv_bfloat16 h0 = __float2bfloat16(v.x), h1 = __float2bfloat16(v.y);
            __nv_bfloat16 h2 = __float2bfloat16(v.z), h3 = __float2bfloat16(v.w);
            uint2 hv = make_uint2(pk2(h0, h1), pk2(h2, h3));
            uint2 lv = make_uint2(
                pk2(__float2bfloat16(v.x - __bfloat162float(h0)),
                    __float2bfloat16(v.y - __bfloat162float(h1))),
                pk2(__float2bfloat16(v.z - __bfloat162float(h2)),
                    __float2bfloat16(v.w - __bfloat162float(h3))));
            *(uint2*)(g_xhi + c * 4) = hv;
            *(uint2*)(g_xlo + c * 4) = lv;
        }
    }
}

// ---------------------------------------------------------------------------
// qkv2: M64 x N128 x K2048 tiles, grid (128, 3), 256 threads, 3 CTAs/SM.
// A (Xbf16) + B (Wbf16) both cp.async double-buffered, KC=32.
// Warp grid 2x4, warp tile 32x32. 3-term split: AhBh + AhBl + AlBh.
// ---------------------------------------------------------------------------
#define KC   32
#define LDB  40
#define ASTG (64 * LDB * 2)          // 5120 B per A stage per buf
#define BSTG (128 * LDB * 2)         // 10240 B per B stage per buf
#define O2_AHI 0
#define O2_ALO (O2_AHI + 2 * ASTG)   // 10240
#define O2_BHI (O2_ALO + 2 * ASTG)   // 20480
#define O2_BLO (O2_BHI + 2 * BSTG)   // 40960
#define O2_BIAS (O2_BLO + 2 * BSTG)  // 61440
#define QSM2_TOTAL (O2_BIAS + 512)   // 61952
// Ct overlays at 0 in epilogue: 64 x 132 floats = 33792 B

__global__ __launch_bounds__(256, 3)
void qkv2(const float* __restrict__ bq, const float* __restrict__ bk,
          const float* __restrict__ bv)
{
    extern __shared__ char smem[];
    const uint32_t sb = smem_u32(smem);
    float* biasS = (float*)(smem + O2_BIAS);

    const int wsel = blockIdx.y;
    const int m0   = blockIdx.x * 64;
    const int t    = threadIdx.x;
    const int wid  = t >> 5, lane = t & 31;
    const int g    = lane >> 2, tig = lane & 3;
    const int wm   = wid >> 2, wn = wid & 3;      // 2 x 4 warps -> 32x32 tiles

    const int ai_off = (((lane >> 3) & 1) * 8 + (lane & 7)) * LDB + (lane >> 4) * 8;
    const int bi_off = ((lane >> 4) * 8 + (lane & 7)) * LDB + ((lane >> 3) & 1) * 8;

    if (t < 128) {
        const float* bias = (wsel == 0) ? bq : (wsel == 1 ? bk : bv);
        biasS[t] = bias[t];
    }

    const __nv_bfloat16* gXh = g_xhi;
    const __nv_bfloat16* gXl = g_xlo;
    const __nv_bfloat16* WH = g_Whi + (size_t)wsel * HD * EMBED;
    const __nv_bfloat16* WL = g_Wlo + (size_t)wsel * HD * EMBED;

    // cp.async mappings
    const int arow = (t >> 1) & 63, abuf = t >> 7;   // 128 units x 2 halves? ->
    const int ahalf = t & 1;                          // t = unit*2+half; unit = row + 64*buf
    const int brow = t & 127, bbuf = t >> 7;

    float c[2][4][4];
    #pragma unroll
    for (int i = 0; i < 2; ++i)
        #pragma unroll
        for (int j = 0; j < 4; ++j)
            #pragma unroll
            for (int q = 0; q < 4; ++q) c[i][j][q] = 0.f;

    // ---- prologue: issue stages 0,1
    #pragma unroll
    for (int pi = 0; pi < 2; ++pi) {
        const int kb = pi * KC;
        {   // A: unit = (t>>1): row=unit&63, buf=unit>>6; half = t&1 (32B)
            const int unit = t >> 1;
            const int row = unit & 63, buf = unit >> 6;
            const __nv_bfloat16* src = (buf ? gXl : gXh)
                + (size_t)(m0 + row) * EMBED + kb + ahalf * 16;
            const uint32_t dst = sb + (buf ? O2_ALO : O2_AHI) + pi * ASTG
                + row * (LDB * 2) + ahalf * 32;
            cpa16(dst, src);
            cpa16(dst + 16, src + 8);
        }
        {   // B: row = t&127, buf = t>>7; 64B per thread
            const __nv_bfloat16* src = (bbuf ? WL : WH)
                + (size_t)brow * EMBED + kb;
            const uint32_t dst = sb + (bbuf ? O2_BLO : O2_BHI) + pi * BSTG
                + brow * (LDB * 2);
            #pragma unroll
            for (int j = 0; j < 4; ++j) cpa16(dst + j * 16, src + j * 8);
        }
        CP_COMMIT();
    }

    for (int kt = 0; kt < EMBED / KC; ++kt) {
        const int st = kt & 1;
        const uint32_t sAhi = sb + O2_AHI + st * ASTG;
        const uint32_t sAlo = sb + O2_ALO + st * ASTG;
        const uint32_t sBhi = sb + O2_BHI + st * BSTG;
        const uint32_t sBlo = sb + O2_BLO + st * BSTG;

        CP_WAIT1();
        __syncthreads();

        #pragma unroll
        for (int ks = 0; ks < 2; ++ks) {
            const int k0s = ks * 16;
            uint32_t ah[2][4], al[2][4], bh[2][4], bl[2][4];
            #pragma unroll
            for (int mi = 0; mi < 2; ++mi) {
                const uint32_t ro = 2 * ((wm * 32 + mi * 16) * LDB + k0s + ai_off);
                ldsm4(ah[mi], sAhi + ro);
                ldsm4(al[mi], sAlo + ro);
            }
            #pragma unroll
            for (int h = 0; h < 2; ++h) {
                const uint32_t ro = 2 * ((wn * 32 + h * 16) * LDB + k0s + bi_off);
                ldsm4(bh[h], sBhi + ro);
                ldsm4(bl[h], sBlo + ro);
            }
            #pragma unroll
            for (int mi = 0; mi < 2; ++mi)
                #pragma unroll
                for (int nt = 0; nt < 4; ++nt) {
                    const uint32_t* bhp = &bh[nt >> 1][(nt & 1) * 2];
                    const uint32_t* blp = &bl[nt >> 1][(nt & 1) * 2];
                    mma16816(c[mi][nt], ah[mi], bhp);
                    mma16816(c[mi][nt], ah[mi], blp);
                    mma16816(c[mi][nt], al[mi], bhp);
                }
        }
        __syncthreads();

        // issue kt+2 into stage st
        if (kt + 2 < EMBED / KC) {
            const int kb = (kt + 2) * KC;
            {
                const int unit = t >> 1;
                const int row = unit & 63, buf = unit >> 6;
                const __nv_bfloat16* src = (buf ? gXl : gXh)
                    + (size_t)(m0 + row) * EMBED + kb + ahalf * 16;
                const uint32_t dst = sb + (buf ? O2_ALO : O2_AHI) + st * ASTG
                    + row * (LDB * 2) + ahalf * 32;
                cpa16(dst, src);
                cpa16(dst + 16, src + 8);
            }
            {
                const __nv_bfloat16* src = (bbuf ? WL : WH)
                    + (size_t)brow * EMBED + kb;
                const uint32_t dst = sb + (bbuf ? O2_BLO : O2_BHI) + st * BSTG
                    + brow * (LDB * 2);
                #pragma unroll
                for (int j = 0; j < 4; ++j) cpa16(dst + j * 16, src + j * 8);
            }
        }
        CP_COMMIT();
    }

    // ---- epilogue: frags (+bias) -> Ct (overlays A/B smem), then gmem bf16
    __syncthreads();
    float (*Ct)[132] = (float (*)[132])smem;
    #pragma unroll
    for (int mi = 0; mi < 2; ++mi) {
        const int r = wm * 32 + mi * 16 + g;
        #pragma unroll
        for (int nt = 0; nt < 4; ++nt) {
            const int n = wn * 32 + nt * 8 + tig * 2;
            Ct[r][n]         = c[mi][nt][0] + biasS[n];
            Ct[r][n + 1]     = c[mi][nt][1] + biasS[n + 1];
            Ct[r + 8][n]     = c[mi][nt][2] + biasS[n];
            Ct[r + 8][n + 1] = c[mi][nt][3] + biasS[n + 1];
        }
    }
    __syncthreads();

    const int batch = m0 >> 11, s0 = m0 & 2047;
    if (wsel < 2) {
        // [b][s][d]: thread -> row r = t>>2 (0..63), d-chunk (t&3)*32
        const int r = t >> 2, dq = (t & 3) * 32;
        __nv_bfloat16* dhi = (wsel == 0 ? g_qhi : g_khi)
            + ((size_t)batch * SEQ + s0 + r) * HD + dq;
        __nv_bfloat16* dlo = (wsel == 0 ? g_qlo : g_klo)
            + ((size_t)batch * SEQ + s0 + r) * HD + dq;
        #pragma unroll
        for (int qq = 0; qq < 4; ++qq) {
            uint32_t hp[4], lp[4];
            #pragma unroll
            for (int e = 0; e < 4; ++e) {
                float x0 = Ct[r][dq + qq * 8 + e * 2];
                float x1 = Ct[r][dq + qq * 8 + e * 2 + 1];
                __nv_bfloat16 h0 = __float2bfloat16(x0);
                __nv_bfloat16 h1 = __float2bfloat16(x1);
                hp[e] = pk2(h0, h1);
                lp[e] = pk2(__float2bfloat16(x0 - __bfloat162float(h0)),
                            __float2bfloat16(x1 - __bfloat162float(h1)));
            }
            *(uint4*)(dhi + qq * 8) = make_uint4(hp[0], hp[1], hp[2], hp[3]);
            *(uint4*)(dlo + qq * 8) = make_uint4(lp[0], lp[1], lp[2], lp[3]);
        }
    } else {
        // transposed [b][d][s]: thread -> d = t>>1 (0..127), s-chunk (t&1)*32
        const int d = t >> 1, sch = (t & 1) * 32;
        size_t base = ((size_t)batch * HD + d) * SEQ + s0 + sch;
        #pragma unroll
        for (int qq = 0; qq < 4; ++qq) {
            uint32_t hp[4], lp[4];
            #pragma unroll
            for (int e = 0; e < 4; ++e) {
                float x0 = Ct[sch + qq * 8 + e * 2][d];
                float x1 = Ct[sch + qq * 8 + e * 2 + 1][d];
                __nv_bfloat16 h0 = __float2bfloat16(x0);
                __nv_bfloat16 h1 = __float2bfloat16(x1);
                hp[e] = pk2(h0, h1);
                lp[e] = pk2(__float2bfloat16(x0 - __bfloat162float(h0)),
                            __float2bfloat16(x1 - __bfloat162float(h1)));
            }
            *(uint4*)(g_vthi + base + qq * 8) = make_uint4(hp[0], hp[1], hp[2], hp[3]);
            *(uint4*)(g_vtlo + base + qq * 8) = make_uint4(lp[0], lp[1], lp[2], lp[3]);
        }
    }
}

// ---------------------------------------------------------------------------
// Attention v4 (unchanged from round 6, passing): cp.async 2-stage pipeline,
// 64-wide k-subtiles, mma.sync bf16 3-term splits, balanced causal pairing.
// ---------------------------------------------------------------------------
#define KT   64
#define LDK  136
#define LDV  72
#define LDP  72
#define SPS  68

#define AO_QHI  0
#define AO_QLO  (AO_QHI + 32 * LDK * 2)
#define AO_KHI  (AO_QLO + 32 * LDK * 2)
#define AO_KLO  (AO_KHI + 2 * KT * LDK * 2)
#define AO_VHI  (AO_KLO + 2 * KT * LDK * 2)
#define AO_VLO  (AO_VHI + 2 * HD * LDV * 2)
#define AO_PS   (AO_VLO + 2 * HD * LDV * 2)
#define AO_PB   (AO_PS  + 32 * SPS * 4)
#define AO_PBL  (AO_PB  + 32 * LDP * 2)
#define AO_MLA  (AO_PBL + 32 * LDP * 2)
#define ASM_TOTAL (AO_MLA + 3 * 32 * 4)

__global__ __launch_bounds__(256)
void attn4(float* __restrict__ out)
{
    extern __shared__ char smem[];
    const uint32_t sb = smem_u32(smem);
    float* Ps   = (float*)(smem + AO_PS);
    float* m_s  = (float*)(smem + AO_MLA);
    float* l_s  = m_s + 32;
    float* al_s = l_s + 32;

    const int b = blockIdx.y, t = threadIdx.x;
    const int wid = t >> 5, lane = t & 31;
    const int g = lane >> 2, tig = lane & 3;
    const int wm = wid & 1, wn = wid >> 1;

    const int aiQ = (((lane >> 3) & 1) * 8 + (lane & 7)) * LDK + (lane >> 4) * 8;
    const int biK = ((lane >> 4) * 8 + (lane & 7)) * LDK + ((lane >> 3) & 1) * 8;
    const int aiP = (((lane >> 3) & 1) * 8 + (lane & 7)) * LDP + (lane >> 4) * 8;
    const int biV = ((lane >> 4) * 8 + (lane & 7)) * LDV + ((lane >> 3) & 1) * 8;

    const __nv_bfloat16* gQh = g_qhi + (size_t)b * SEQ * HD;
    const __nv_bfloat16* gQl = g_qlo + (size_t)b * SEQ * HD;
    const __nv_bfloat16* gKh = g_khi + (size_t)b * SEQ * HD;
    const __nv_bfloat16* gKl = g_klo + (size_t)b * SEQ * HD;
    const __nv_bfloat16* gVh = g_vthi + (size_t)b * HD * SEQ;
    const __nv_bfloat16* gVl = g_vtlo + (size_t)b * HD * SEQ;

    const float RSC = 0.08838834764831845f;
    const int sr = t >> 3, sc0 = (t & 7) * 8;
    const int kr = t >> 2, kq = t & 3;
    const int vr = t >> 1, vhh = t & 1;

    for (int subt = 0; subt < 2; ++subt) {
        const int jt = subt ? (63 - blockIdx.x) : blockIdx.x;
        const int q0 = jt * 32;
        const int iters = (jt >> 1) + 1;

        {
            const int r = t >> 3, dq = (t & 7) * 16;
            const __nv_bfloat16* sh = gQh + (size_t)(q0 + r) * HD + dq;
            const __nv_bfloat16* sl = gQl + (size_t)(q0 + r) * HD + dq;
            *(uint4*)(smem + AO_QHI + (r * LDK + dq) * 2)      = *(const uint4*)sh;
            *(uint4*)(smem + AO_QHI + (r * LDK + dq + 8) * 2)  = *(const uint4*)(sh + 8);
            *(uint4*)(smem + AO_QLO + (r * LDK + dq) * 2)      = *(const uint4*)sl;
            *(uint4*)(smem + AO_QLO + (r * LDK + dq + 8) * 2)  = *(const uint4*)(sl + 8);
        }
        if (t < 32) { m_s[t] = -1e30f; l_s[t] = 0.f; }

        float o[4][4];
        #pragma unroll
        for (int nt = 0; nt < 4; ++nt)
            #pragma unroll
            for (int q = 0; q < 4; ++q) o[nt][q] = 0.f;

        #pragma unroll
        for (int pi = 0; pi < 2; ++pi) {
            if (pi < iters) {
                const int k0 = pi * KT;
                const uint32_t kh_d = sb + AO_KHI + pi * (KT * LDK * 2) + kr * (LDK * 2) + kq * 64;
                const uint32_t kl_d = sb + AO_KLO + pi * (KT * LDK * 2) + kr * (LDK * 2) + kq * 64;
                const uint32_t vh_d = sb + AO_VHI + pi * (HD * LDV * 2) + vr * (LDV * 2) + vhh * 64;
                const uint32_t vl_d = sb + AO_VLO + pi * (HD * LDV * 2) + vr * (LDV * 2) + vhh * 64;
                const __nv_bfloat16* ksh = gKh + (size_t)(k0 + kr) * HD + kq * 32;
                const __nv_bfloat16* ksl = gKl + (size_t)(k0 + kr) * HD + kq * 32;
                const __nv_bfloat16* vsh = gVh + (size_t)vr * SEQ + k0 + vhh * 32;
                const __nv_bfloat16* vsl = gVl + (size_t)vr * SEQ + k0 + vhh * 32;
                #pragma unroll
                for (int j = 0; j < 4; ++j) {
                    cpa16(kh_d + j * 16, ksh + j * 8);
                    cpa16(kl_d + j * 16, ksl + j * 8);
                    cpa16(vh_d + j * 16, vsh + j * 8);
                    cpa16(vl_d + j * 16, vsl + j * 8);
                }
            }
            CP_COMMIT();
        }

        for (int it = 0; it < iters; ++it) {
            const int k0 = it * KT;
            const int st = it & 1;
            const uint32_t sKhi = sb + AO_KHI + st * (KT * LDK * 2);
            const uint32_t sKlo = sb + AO_KLO + st * (KT * LDK * 2);
            const uint32_t sVhi = sb + AO_VHI + st * (HD * LDV * 2);
            const uint32_t sVlo = sb + AO_VLO + st * (HD * LDV * 2);

            CP_WAIT1();
            __syncthreads();

            float s4[2][4];
            #pragma unroll
            for (int nt = 0; nt < 2; ++nt)
                #pragma unroll
                for (int q = 0; q < 4; ++q) s4[nt][q] = 0.f;
            #pragma unroll
            for (int ks = 0; ks < 8; ++ks) {
                const int k0s = ks * 16;
                uint32_t qh[4], ql[4], kh[4], kl[4];
                const uint32_t ao = 2 * (wm * 16 * LDK + k0s + aiQ);
                ldsm4(qh, sb + AO_QHI + ao);
                ldsm4(ql, sb + AO_QLO + ao);
                const uint32_t bo = 2 * (wn * 16 * LDK + k0s + biK);
                ldsm4(kh, sKhi + bo);
                ldsm4(kl, sKlo + bo);
                #pragma unroll
                for (int nt = 0; nt < 2; ++nt) {
                    mma16816(s4[nt], qh, &kh[nt * 2]);
                    mma16816(s4[nt], qh, &kl[nt * 2]);
                    mma16816(s4[nt], ql, &kh[nt * 2]);
                }
            }
            {
                const int row0 = wm * 16 + g;
                #pragma unroll
                for (int nt = 0; nt < 2; ++nt) {
                    const int col = wn * 16 + nt * 8 + tig * 2;
                    *(float2*)&Ps[row0 * SPS + col] = make_float2(s4[nt][0], s4[nt][1]);
                    *(float2*)&Ps[(row0 + 8) * SPS + col] = make_float2(s4[nt][2], s4[nt][3]);
                }
            }
            __syncthreads();

            {
                const int gq = q0 + sr;
                float sv[8];
                float rm = -1e30f;
                #pragma unroll
                for (int j = 0; j < 8; ++j) {
                    float v = Ps[sr * SPS + sc0 + j] * RSC;
                    if (k0 + sc0 + j > gq) v = -1e10f;
                    sv[j] = v;
                    rm = fmaxf(rm, v);
                }
                #pragma unroll
                for (int off = 4; off >= 1; off >>= 1)
                    rm = fmaxf(rm, __shfl_xor_sync(0xffffffffu, rm, off));
                const float mo = m_s[sr];
                const float mn = fmaxf(mo, rm);
                float rs = 0.f;
                uint32_t pph[4], ppl[4];
                #pragma unroll
                for (int j = 0; j < 4; ++j) {
                    float p0 = __expf(sv[2 * j] - mn);
                    float p1 = __expf(sv[2 * j + 1] - mn);
                    rs += p0 + p1;
                    __nv_bfloat16 h0 = __float2bfloat16(p0);
                    __nv_bfloat16 h1 = __float2bfloat16(p1);
                    pph[j] = pk2(h0, h1);
                    ppl[j] = pk2(__float2bfloat16(p0 - __bfloat162float(h0)),
                                 __float2bfloat16(p1 - __bfloat162float(h1)));
                }
                #pragma unroll
                for (int off = 4; off >= 1; off >>= 1)
                    rs += __shfl_xor_sync(0xffffffffu, rs, off);
                *(uint4*)(smem + AO_PB  + (sr * LDP + sc0) * 2) =
                    make_uint4(pph[0], pph[1], pph[2], pph[3]);
                *(uint4*)(smem + AO_PBL + (sr * LDP + sc0) * 2) =
                    make_uint4(ppl[0], ppl[1], ppl[2], ppl[3]);
                if ((t & 7) == 0) {
                    const float al = __expf(mo - mn);
                    m_s[sr]  = mn;
                    al_s[sr] = al;
                    l_s[sr]  = l_s[sr] * al + rs;
                }
            }
            __syncthreads();

            {
                const float a0 = al_s[wm * 16 + g];
                const float a1 = al_s[wm * 16 + g + 8];
                #pragma unroll
                for (int nt = 0; nt < 4; ++nt) {
                    o[nt][0] *= a0; o[nt][1] *= a0;
                    o[nt][2] *= a1; o[nt][3] *= a1;
                }
                #pragma unroll
                for (int ks = 0; ks < 4; ++ks) {
                    const int k0s = ks * 16;
                    uint32_t pa[4], pal[4], vh[2][4], vl[2][4];
                    const uint32_t po = 2 * (wm * 16 * LDP + k0s + aiP);
                    ldsm4(pa,  sb + AO_PB  + po);
                    ldsm4(pal, sb + AO_PBL + po);
                    #pragma unroll
                    for (int h = 0; h < 2; ++h) {
                        const uint32_t bo = 2 * ((wn * 32 + h * 16) * LDV + k0s + biV);
                        ldsm4(vh[h], sVhi + bo);
                        ldsm4(vl[h], sVlo + bo);
                    }
                    #pragma unroll
                    for (int nt = 0; nt < 4; ++nt) {
                        const uint32_t* vhp = &vh[nt >> 1][(nt & 1) * 2];
                        const uint32_t* vlp = &vl[nt >> 1][(nt & 1) * 2];
                        mma16816(o[nt], pa,  vhp);
                        mma16816(o[nt], pa,  vlp);
                        mma16816(o[nt], pal, vhp);
                    }
                }
            }
            __syncthreads();

            if (it + 2 < iters) {
                const int kn = (it + 2) * KT;
                const uint32_t kh_d = sb + AO_KHI + st * (KT * LDK * 2) + kr * (LDK * 2) + kq * 64;
                const uint32_t kl_d = sb + AO_KLO + st * (KT * LDK * 2) + kr * (LDK * 2) + kq * 64;
                const uint32_t vh_d = sb + AO_VHI + st * (HD * LDV * 2) + vr * (LDV * 2) + vhh * 64;
                const uint32_t vl_d = sb + AO_VLO + st * (HD * LDV * 2) + vr * (LDV * 2) + vhh * 64;
                const __nv_bfloat16* ksh = gKh + (size_t)(kn + kr) * HD + kq * 32;
                const __nv_bfloat16* ksl = gKl + (size_t)(kn + kr) * HD + kq * 32;
                const __nv_bfloat16* vsh = gVh + (size_t)vr * SEQ + kn + vhh * 32;
                const __nv_bfloat16* vsl = gVl + (size_t)vr * SEQ + kn + vhh * 32;
                #pragma unroll
                for (int j = 0; j < 4; ++j) {
                    cpa16(kh_d + j * 16, ksh + j * 8);
                    cpa16(kl_d + j * 16, ksl + j * 8);
                    cpa16(vh_d + j * 16, vsh + j * 8);
                    cpa16(vl_d + j * 16, vsl + j * 8);
                }
            }
            CP_COMMIT();
        }

        {
            const float li0 = 1.f / l_s[wm * 16 + g];
            const float li1 = 1.f / l_s[wm * 16 + g + 8];
            float* op0 = out + ((size_t)b * SEQ + q0 + wm * 16 + g) * HD;
            float* op1 = op0 + 8 * HD;
            #pragma unroll
            for (int nt = 0; nt < 4; ++nt) {
                const int d = wn * 32 + nt * 8 + tig * 2;
                *(float2*)(op0 + d) = make_float2(o[nt][0] * li0, o[nt][1] * li0);
                *(float2*)(op1 + d) = make_float2(o[nt][2] * li1, o[nt][3] * li1);
            }
        }
        __syncthreads();
    }
}

// ---------------------------------------------------------------------------
extern "C" void kernel_launch(void* const* d_in, const int* in_sizes, int n_in,
                              void* d_out, int out_size)
{
    const float* X  = (const float*)d_in[0];
    const float* Wq = (const float*)d_in[1];
    const float* bq = (const float*)d_in[2];
    const float* Wk = (const float*)d_in[3];
    const float* bk = (const float*)d_in[4];
    const float* Wv = (const float*)d_in[5];
    const float* bv = (const float*)d_in[6];
    float* out = (float*)d_out;

    prep_all<<<272, 256>>>(X, Wq, Wk, Wv);

    cudaFuncSetAttribute(qkv2, cudaFuncAttributeMaxDynamicSharedMemorySize,
                         QSM2_TOTAL);
    qkv2<<<dim3(128, 3), 256, QSM2_TOTAL>>>(bq, bk, bv);

    cudaFuncSetAttribute(attn4, cudaFuncAttributeMaxDynamicSharedMemorySize,
                         ASM_TOTAL);
    attn4<<<dim3(32, 4), 256, ASM_TOTAL>>>(out);
}

// round 8
// speedup vs baseline: 1.1683x; 1.1683x over previous
#include <cuda_runtime.h>
#include <cuda_bf16.h>
#include <cstdint>

#define EMBED 2048
#define HD    128
#define NB    4
#define SEQ   2048

// ---------------------------------------------------------------------------
// Scratch globals
// ---------------------------------------------------------------------------
__device__ __align__(16) float g_x [(size_t)NB * SEQ * EMBED];  // rna-tf32 [row][k]
__device__ __align__(16) float g_Wt[3 * HD * EMBED];            // rna-tf32 [w][n][k]
__device__ __align__(16) __nv_bfloat16 g_qhi[NB * SEQ * HD];    // [b][s][d]
__device__ __align__(16) __nv_bfloat16 g_qlo[NB * SEQ * HD];
__device__ __align__(16) __nv_bfloat16 g_khi[NB * SEQ * HD];    // [b][s][d]
__device__ __align__(16) __nv_bfloat16 g_klo[NB * SEQ * HD];
__device__ __align__(16) __nv_bfloat16 g_vthi[NB * HD * SEQ];   // [b][d][s]
__device__ __align__(16) __nv_bfloat16 g_vtlo[NB * HD * SEQ];

__device__ __forceinline__ uint32_t pk2(__nv_bfloat16 a, __nv_bfloat16 b) {
    return ((uint32_t)__bfloat16_as_ushort(b) << 16) | __bfloat16_as_ushort(a);
}
__device__ __forceinline__ uint32_t smem_u32(const void* p) {
    uint32_t a;
    asm("{ .reg .u64 t; cvta.to.shared.u64 t, %1; cvt.u32.u64 %0, t; }"
        : "=r"(a) : "l"(p));
    return a;
}
__device__ __forceinline__ float tf32rna(float x) {
    uint32_t r;
    asm("cvt.rna.tf32.f32 %0, %1;" : "=r"(r) : "f"(x));
    return __uint_as_float(r);
}
// bf16 m16n8k16
__device__ __forceinline__ void mma16816(float* c, const uint32_t* a,
                                         const uint32_t* b) {
    asm volatile(
        "mma.sync.aligned.m16n8k16.row.col.f32.bf16.bf16.f32 "
        "{%0,%1,%2,%3}, {%4,%5,%6,%7}, {%8,%9}, {%0,%1,%2,%3};"
        : "+f"(c[0]), "+f"(c[1]), "+f"(c[2]), "+f"(c[3])
        : "r"(a[0]), "r"(a[1]), "r"(a[2]), "r"(a[3]), "r"(b[0]), "r"(b[1]));
}
// tf32 m16n8k8 (fragments loaded via b16 ldmatrix on fp32 data)
__device__ __forceinline__ void mma1688t(float* c, const uint32_t* a,
                                         const uint32_t* b) {
    asm volatile(
        "mma.sync.aligned.m16n8k8.row.col.f32.tf32.tf32.f32 "
        "{%0,%1,%2,%3}, {%4,%5,%6,%7}, {%8,%9}, {%0,%1,%2,%3};"
        : "+f"(c[0]), "+f"(c[1]), "+f"(c[2]), "+f"(c[3])
        : "r"(a[0]), "r"(a[1]), "r"(a[2]), "r"(a[3]), "r"(b[0]), "r"(b[1]));
}
__device__ __forceinline__ void ldsm4(uint32_t* r, uint32_t saddr) {
    asm volatile("ldmatrix.sync.aligned.m8n8.x4.shared.b16 {%0,%1,%2,%3}, [%4];"
                 : "=r"(r[0]), "=r"(r[1]), "=r"(r[2]), "=r"(r[3]) : "r"(saddr));
}
__device__ __forceinline__ void cpa16(uint32_t dst, const void* src) {
    asm volatile("cp.async.cg.shared.global [%0], [%1], 16;"
                 :: "r"(dst), "l"(__cvta_generic_to_global(src)) : "memory");
}
#define CP_COMMIT() asm volatile("cp.async.commit_group;" ::: "memory")
#define CP_WAIT1()  asm volatile("cp.async.wait_group 1;" ::: "memory")

// ---------------------------------------------------------------------------
// prep3: blocks 0..47   -> W fp32 [k][n] -> rna-tf32 fp32 [w][n][k]
//        blocks 48..1023 -> X fp32 -> rna-tf32 fp32 (in g_x)
// ---------------------------------------------------------------------------
__global__ __launch_bounds__(256)
void prep3(const float* __restrict__ X,
           const float* __restrict__ Wq, const float* __restrict__ Wk,
           const float* __restrict__ Wv)
{
    const int t = threadIdx.x;
    if (blockIdx.x < 48) {
        __shared__ float Ws[128][132];
        const int w  = blockIdx.x >> 4;
        const int k0 = (blockIdx.x & 15) * 128;
        const float* __restrict__ W = (w == 0) ? Wq : (w == 1 ? Wk : Wv);

        for (int l = 0; l < 64; ++l) {
            int idx = t + l * 256;
            int kk = idx >> 7, n = idx & 127;
            Ws[kk][n] = W[(size_t)(k0 + kk) * HD + n];
        }
        __syncthreads();

        const int n = t >> 1, kh = (t & 1) * 64;
        float* dst = g_Wt + (size_t)w * HD * EMBED + (size_t)n * EMBED + k0 + kh;
        #pragma unroll
        for (int g = 0; g < 16; ++g) {
            float4 v = make_float4(tf32rna(Ws[kh + g * 4 + 0][n]),
                                   tf32rna(Ws[kh + g * 4 + 1][n]),
                                   tf32rna(Ws[kh + g * 4 + 2][n]),
                                   tf32rna(Ws[kh + g * 4 + 3][n]));
            *(float4*)(dst + g * 4) = v;
        }
    } else {
        const size_t N4 = (size_t)NB * SEQ * EMBED / 4;
        const size_t nthr = 976 * 256;
        size_t c = (size_t)(blockIdx.x - 48) * 256 + t;
        for (; c < N4; c += nthr) {
            float4 v = *(const float4*)(X + c * 4);
            v.x = tf32rna(v.x); v.y = tf32rna(v.y);
            v.z = tf32rna(v.z); v.w = tf32rna(v.w);
            *(float4*)(g_x + c * 4) = v;
        }
    }
}

// ---------------------------------------------------------------------------
// qkv3: single-term TF32 GEMM. M64 x N128 x K2048, grid (128, 3), 256 thr.
// A (X) + B (W) cp.async double-buffered fp32, KC=32 (4 k8 steps).
// Fragments via b16 ldmatrix on fp32 data (tf32-compatible layout).
// ---------------------------------------------------------------------------
#define KC    32
#define LDW   36                      // floats per row (32 + 4 pad) = 144 B
#define LDW16 72                      // same row stride in b16 units
#define A3STG (64 * LDW * 4)          // 9216 B per A stage
#define B3STG (128 * LDW * 4)         // 18432 B per B stage
#define O3_A  0
#define O3_B  (2 * A3STG)             // 18432
#define O3_BIAS (O3_B + 2 * B3STG)    // 55296
#define QSM3_TOTAL (O3_BIAS + 512)    // 55808
// epilogue Ct overlay at 0: 64 x 132 floats = 33792 B

__global__ __launch_bounds__(256, 3)
void qkv3(const float* __restrict__ bq, const float* __restrict__ bk,
          const float* __restrict__ bv)
{
    extern __shared__ char smem[];
    const uint32_t sb = smem_u32(smem);
    float* biasS = (float*)(smem + O3_BIAS);

    const int wsel = blockIdx.y;
    const int m0   = blockIdx.x * 64;
    const int t    = threadIdx.x;
    const int wid  = t >> 5, lane = t & 31;
    const int g    = lane >> 2, tig = lane & 3;
    const int wm   = wid >> 2, wn = wid & 3;      // 2 x 4 warps -> 32x32 tiles

    // b16-unit lane offsets (row-within-tile * 72 + col-halves)
    const int aiA = (((lane >> 3) & 1) * 8 + (lane & 7)) * LDW16 + (lane >> 4) * 8;
    const int biB = ((lane >> 4) * 8 + (lane & 7)) * LDW16 + ((lane >> 3) & 1) * 8;

    if (t < 128) {
        const float* bias = (wsel == 0) ? bq : (wsel == 1 ? bk : bv);
        biasS[t] = bias[t];
    }

    const float* Wt = g_Wt + (size_t)wsel * HD * EMBED;

    // cp.async mappings
    const int ar = t >> 2, ac = t & 3;   // A: row 0..63, 32B chunk
    const int br = t >> 1, bh = t & 1;   // B: row 0..127, 64B half

    float c[2][4][4];
    #pragma unroll
    for (int i = 0; i < 2; ++i)
        #pragma unroll
        for (int j = 0; j < 4; ++j)
            #pragma unroll
            for (int q = 0; q < 4; ++q) c[i][j][q] = 0.f;

    // ---- prologue: stages 0,1
    #pragma unroll
    for (int pi = 0; pi < 2; ++pi) {
        const int kb = pi * KC;
        {
            const float* src = g_x + (size_t)(m0 + ar) * EMBED + kb + ac * 8;
            const uint32_t dst = sb + O3_A + pi * A3STG + ar * (LDW * 4) + ac * 32;
            cpa16(dst, src);
            cpa16(dst + 16, src + 4);
        }
        {
            const float* src = Wt + (size_t)br * EMBED + kb + bh * 16;
            const uint32_t dst = sb + O3_B + pi * B3STG + br * (LDW * 4) + bh * 64;
            #pragma unroll
            for (int j = 0; j < 4; ++j) cpa16(dst + j * 16, src + j * 4);
        }
        CP_COMMIT();
    }

    for (int kt = 0; kt < EMBED / KC; ++kt) {
        const int st = kt & 1;
        const uint32_t sA = sb + O3_A + st * A3STG;
        const uint32_t sB = sb + O3_B + st * B3STG;

        CP_WAIT1();
        __syncthreads();

        #pragma unroll
        for (int ks = 0; ks < 4; ++ks) {
            const int ko = ks * 16;     // b16 units = 8 tf32
            uint32_t a[2][4], bb[2][4];
            #pragma unroll
            for (int mi = 0; mi < 2; ++mi)
                ldsm4(a[mi], sA + 2 * ((wm * 32 + mi * 16) * LDW16 + ko + aiA));
            #pragma unroll
            for (int h = 0; h < 2; ++h)
                ldsm4(bb[h], sB + 2 * ((wn * 32 + h * 16) * LDW16 + ko + biB));
            #pragma unroll
            for (int mi = 0; mi < 2; ++mi)
                #pragma unroll
                for (int nt = 0; nt < 4; ++nt)
                    mma1688t(c[mi][nt], a[mi], &bb[nt >> 1][(nt & 1) * 2]);
        }
        __syncthreads();

        if (kt + 2 < EMBED / KC) {
            const int kb = (kt + 2) * KC;
            {
                const float* src = g_x + (size_t)(m0 + ar) * EMBED + kb + ac * 8;
                const uint32_t dst = sb + O3_A + st * A3STG + ar * (LDW * 4) + ac * 32;
                cpa16(dst, src);
                cpa16(dst + 16, src + 4);
            }
            {
                const float* src = Wt + (size_t)br * EMBED + kb + bh * 16;
                const uint32_t dst = sb + O3_B + st * B3STG + br * (LDW * 4) + bh * 64;
                #pragma unroll
                for (int j = 0; j < 4; ++j) cpa16(dst + j * 16, src + j * 4);
            }
        }
        CP_COMMIT();
    }

    // ---- epilogue: frags (+bias) -> Ct -> bf16 hi/lo gmem
    __syncthreads();
    float (*Ct)[132] = (float (*)[132])smem;
    #pragma unroll
    for (int mi = 0; mi < 2; ++mi) {
        const int r = wm * 32 + mi * 16 + g;
        #pragma unroll
        for (int nt = 0; nt < 4; ++nt) {
            const int n = wn * 32 + nt * 8 + tig * 2;
            Ct[r][n]         = c[mi][nt][0] + biasS[n];
            Ct[r][n + 1]     = c[mi][nt][1] + biasS[n + 1];
            Ct[r + 8][n]     = c[mi][nt][2] + biasS[n];
            Ct[r + 8][n + 1] = c[mi][nt][3] + biasS[n + 1];
        }
    }
    __syncthreads();

    const int batch = m0 >> 11, s0 = m0 & 2047;
    if (wsel < 2) {
        const int r = t >> 2, dq = (t & 3) * 32;
        __nv_bfloat16* dhi = (wsel == 0 ? g_qhi : g_khi)
            + ((size_t)batch * SEQ + s0 + r) * HD + dq;
        __nv_bfloat16* dlo = (wsel == 0 ? g_qlo : g_klo)
            + ((size_t)batch * SEQ + s0 + r) * HD + dq;
        #pragma unroll
        for (int qq = 0; qq < 4; ++qq) {
            uint32_t hp[4], lp[4];
            #pragma unroll
            for (int e = 0; e < 4; ++e) {
                float x0 = Ct[r][dq + qq * 8 + e * 2];
                float x1 = Ct[r][dq + qq * 8 + e * 2 + 1];
                __nv_bfloat16 h0 = __float2bfloat16(x0);
                __nv_bfloat16 h1 = __float2bfloat16(x1);
                hp[e] = pk2(h0, h1);
                lp[e] = pk2(__float2bfloat16(x0 - __bfloat162float(h0)),
                            __float2bfloat16(x1 - __bfloat162float(h1)));
            }
            *(uint4*)(dhi + qq * 8) = make_uint4(hp[0], hp[1], hp[2], hp[3]);
            *(uint4*)(dlo + qq * 8) = make_uint4(lp[0], lp[1], lp[2], lp[3]);
        }
    } else {
        const int d = t >> 1, sch = (t & 1) * 32;
        size_t base = ((size_t)batch * HD + d) * SEQ + s0 + sch;
        #pragma unroll
        for (int qq = 0; qq < 4; ++qq) {
            uint32_t hp[4], lp[4];
            #pragma unroll
            for (int e = 0; e < 4; ++e) {
                float x0 = Ct[sch + qq * 8 + e * 2][d];
                float x1 = Ct[sch + qq * 8 + e * 2 + 1][d];
                __nv_bfloat16 h0 = __float2bfloat16(x0);
                __nv_bfloat16 h1 = __float2bfloat16(x1);
                hp[e] = pk2(h0, h1);
                lp[e] = pk2(__float2bfloat16(x0 - __bfloat162float(h0)),
                            __float2bfloat16(x1 - __bfloat162float(h1)));
            }
            *(uint4*)(g_vthi + base + qq * 8) = make_uint4(hp[0], hp[1], hp[2], hp[3]);
            *(uint4*)(g_vtlo + base + qq * 8) = make_uint4(lp[0], lp[1], lp[2], lp[3]);
        }
    }
}

// ---------------------------------------------------------------------------
// Attention v4 (unchanged, passing): cp.async 2-stage pipeline, 64-wide
// k-subtiles, mma.sync bf16 3-term splits, balanced causal pairing.
// ---------------------------------------------------------------------------
#define KT   64
#define LDK  136
#define LDV  72
#define LDP  72
#define SPS  68

#define AO_QHI  0
#define AO_QLO  (AO_QHI + 32 * LDK * 2)
#define AO_KHI  (AO_QLO + 32 * LDK * 2)
#define AO_KLO  (AO_KHI + 2 * KT * LDK * 2)
#define AO_VHI  (AO_KLO + 2 * KT * LDK * 2)
#define AO_VLO  (AO_VHI + 2 * HD * LDV * 2)
#define AO_PS   (AO_VLO + 2 * HD * LDV * 2)
#define AO_PB   (AO_PS  + 32 * SPS * 4)
#define AO_PBL  (AO_PB  + 32 * LDP * 2)
#define AO_MLA  (AO_PBL + 32 * LDP * 2)
#define ASM_TOTAL (AO_MLA + 3 * 32 * 4)

__global__ __launch_bounds__(256)
void attn4(float* __restrict__ out)
{
    extern __shared__ char smem[];
    const uint32_t sb = smem_u32(smem);
    float* Ps   = (float*)(smem + AO_PS);
    float* m_s  = (float*)(smem + AO_MLA);
    float* l_s  = m_s + 32;
    float* al_s = l_s + 32;

    const int b = blockIdx.y, t = threadIdx.x;
    const int wid = t >> 5, lane = t & 31;
    const int g = lane >> 2, tig = lane & 3;
    const int wm = wid & 1, wn = wid >> 1;

    const int aiQ = (((lane >> 3) & 1) * 8 + (lane & 7)) * LDK + (lane >> 4) * 8;
    const int biK = ((lane >> 4) * 8 + (lane & 7)) * LDK + ((lane >> 3) & 1) * 8;
    const int aiP = (((lane >> 3) & 1) * 8 + (lane & 7)) * LDP + (lane >> 4) * 8;
    const int biV = ((lane >> 4) * 8 + (lane & 7)) * LDV + ((lane >> 3) & 1) * 8;

    const __nv_bfloat16* gQh = g_qhi + (size_t)b * SEQ * HD;
    const __nv_bfloat16* gQl = g_qlo + (size_t)b * SEQ * HD;
    const __nv_bfloat16* gKh = g_khi + (size_t)b * SEQ * HD;
    const __nv_bfloat16* gKl = g_klo + (size_t)b * SEQ * HD;
    const __nv_bfloat16* gVh = g_vthi + (size_t)b * HD * SEQ;
    const __nv_bfloat16* gVl = g_vtlo + (size_t)b * HD * SEQ;

    const float RSC = 0.08838834764831845f;
    const int sr = t >> 3, sc0 = (t & 7) * 8;
    const int kr = t >> 2, kq = t & 3;
    const int vr = t >> 1, vhh = t & 1;

    for (int subt = 0; subt < 2; ++subt) {
        const int jt = subt ? (63 - blockIdx.x) : blockIdx.x;
        const int q0 = jt * 32;
        const int iters = (jt >> 1) + 1;

        {
            const int r = t >> 3, dq = (t & 7) * 16;
            const __nv_bfloat16* sh = gQh + (size_t)(q0 + r) * HD + dq;
            const __nv_bfloat16* sl = gQl + (size_t)(q0 + r) * HD + dq;
            *(uint4*)(smem + AO_QHI + (r * LDK + dq) * 2)      = *(const uint4*)sh;
            *(uint4*)(smem + AO_QHI + (r * LDK + dq + 8) * 2)  = *(const uint4*)(sh + 8);
            *(uint4*)(smem + AO_QLO + (r * LDK + dq) * 2)      = *(const uint4*)sl;
            *(uint4*)(smem + AO_QLO + (r * LDK + dq + 8) * 2)  = *(const uint4*)(sl + 8);
        }
        if (t < 32) { m_s[t] = -1e30f; l_s[t] = 0.f; }

        float o[4][4];
        #pragma unroll
        for (int nt = 0; nt < 4; ++nt)
            #pragma unroll
            for (int q = 0; q < 4; ++q) o[nt][q] = 0.f;

        #pragma unroll
        for (int pi = 0; pi < 2; ++pi) {
            if (pi < iters) {
                const int k0 = pi * KT;
                const uint32_t kh_d = sb + AO_KHI + pi * (KT * LDK * 2) + kr * (LDK * 2) + kq * 64;
                const uint32_t kl_d = sb + AO_KLO + pi * (KT * LDK * 2) + kr * (LDK * 2) + kq * 64;
                const uint32_t vh_d = sb + AO_VHI + pi * (HD * LDV * 2) + vr * (LDV * 2) + vhh * 64;
                const uint32_t vl_d = sb + AO_VLO + pi * (HD * LDV * 2) + vr * (LDV * 2) + vhh * 64;
                const __nv_bfloat16* ksh = gKh + (size_t)(k0 + kr) * HD + kq * 32;
                const __nv_bfloat16* ksl = gKl + (size_t)(k0 + kr) * HD + kq * 32;
                const __nv_bfloat16* vsh = gVh + (size_t)vr * SEQ + k0 + vhh * 32;
                const __nv_bfloat16* vsl = gVl + (size_t)vr * SEQ + k0 + vhh * 32;
                #pragma unroll
                for (int j = 0; j < 4; ++j) {
                    cpa16(kh_d + j * 16, ksh + j * 8);
                    cpa16(kl_d + j * 16, ksl + j * 8);
                    cpa16(vh_d + j * 16, vsh + j * 8);
                    cpa16(vl_d + j * 16, vsl + j * 8);
                }
            }
            CP_COMMIT();
        }

        for (int it = 0; it < iters; ++it) {
            const int k0 = it * KT;
            const int st = it & 1;
            const uint32_t sKhi = sb + AO_KHI + st * (KT * LDK * 2);
            const uint32_t sKlo = sb + AO_KLO + st * (KT * LDK * 2);
            const uint32_t sVhi = sb + AO_VHI + st * (HD * LDV * 2);
            const uint32_t sVlo = sb + AO_VLO + st * (HD * LDV * 2);

            CP_WAIT1();
            __syncthreads();

            float s4[2][4];
            #pragma unroll
            for (int nt = 0; nt < 2; ++nt)
                #pragma unroll
                for (int q = 0; q < 4; ++q) s4[nt][q] = 0.f;
            #pragma unroll
            for (int ks = 0; ks < 8; ++ks) {
                const int k0s = ks * 16;
                uint32_t qh[4], ql[4], kh[4], kl[4];
                const uint32_t ao = 2 * (wm * 16 * LDK + k0s + aiQ);
                ldsm4(qh, sb + AO_QHI + ao);
                ldsm4(ql, sb + AO_QLO + ao);
                const uint32_t bo = 2 * (wn * 16 * LDK + k0s + biK);
                ldsm4(kh, sKhi + bo);
                ldsm4(kl, sKlo + bo);
                #pragma unroll
                for (int nt = 0; nt < 2; ++nt) {
                    mma16816(s4[nt], qh, &kh[nt * 2]);
                    mma16816(s4[nt], qh, &kl[nt * 2]);
                    mma16816(s4[nt], ql, &kh[nt * 2]);
                }
            }
            {
                const int row0 = wm * 16 + g;
                #pragma unroll
                for (int nt = 0; nt < 2; ++nt) {
                    const int col = wn * 16 + nt * 8 + tig * 2;
                    *(float2*)&Ps[row0 * SPS + col] = make_float2(s4[nt][0], s4[nt][1]);
                    *(float2*)&Ps[(row0 + 8) * SPS + col] = make_float2(s4[nt][2], s4[nt][3]);
                }
            }
            __syncthreads();

            {
                const int gq = q0 + sr;
                float sv[8];
                float rm = -1e30f;
                #pragma unroll
                for (int j = 0; j < 8; ++j) {
                    float v = Ps[sr * SPS + sc0 + j] * RSC;
                    if (k0 + sc0 + j > gq) v = -1e10f;
                    sv[j] = v;
                    rm = fmaxf(rm, v);
                }
                #pragma unroll
                for (int off = 4; off >= 1; off >>= 1)
                    rm = fmaxf(rm, __shfl_xor_sync(0xffffffffu, rm, off));
                const float mo = m_s[sr];
                const float mn = fmaxf(mo, rm);
                float rs = 0.f;
                uint32_t pph[4], ppl[4];
                #pragma unroll
                for (int j = 0; j < 4; ++j) {
                    float p0 = __expf(sv[2 * j] - mn);
                    float p1 = __expf(sv[2 * j + 1] - mn);
                    rs += p0 + p1;
                    __nv_bfloat16 h0 = __float2bfloat16(p0);
                    __nv_bfloat16 h1 = __float2bfloat16(p1);
                    pph[j] = pk2(h0, h1);
                    ppl[j] = pk2(__float2bfloat16(p0 - __bfloat162float(h0)),
                                 __float2bfloat16(p1 - __bfloat162float(h1)));
                }
                #pragma unroll
                for (int off = 4; off >= 1; off >>= 1)
                    rs += __shfl_xor_sync(0xffffffffu, rs, off);
                *(uint4*)(smem + AO_PB  + (sr * LDP + sc0) * 2) =
                    make_uint4(pph[0], pph[1], pph[2], pph[3]);
                *(uint4*)(smem + AO_PBL + (sr * LDP + sc0) * 2) =
                    make_uint4(ppl[0], ppl[1], ppl[2], ppl[3]);
                if ((t & 7) == 0) {
                    const float al = __expf(mo - mn);
                    m_s[sr]  = mn;
                    al_s[sr] = al;
                    l_s[sr]  = l_s[sr] * al + rs;
                }
            }
            __syncthreads();

            {
                const float a0 = al_s[wm * 16 + g];
                const float a1 = al_s[wm * 16 + g + 8];
                #pragma unroll
                for (int nt = 0; nt < 4; ++nt) {
                    o[nt][0] *= a0; o[nt][1] *= a0;
                    o[nt][2] *= a1; o[nt][3] *= a1;
                }
                #pragma unroll
                for (int ks = 0; ks < 4; ++ks) {
                    const int k0s = ks * 16;
                    uint32_t pa[4], pal[4], vh[2][4], vl[2][4];
                    const uint32_t po = 2 * (wm * 16 * LDP + k0s + aiP);
                    ldsm4(pa,  sb + AO_PB  + po);
                    ldsm4(pal, sb + AO_PBL + po);
                    #pragma unroll
                    for (int h = 0; h < 2; ++h) {
                        const uint32_t bo = 2 * ((wn * 32 + h * 16) * LDV + k0s + biV);
                        ldsm4(vh[h], sVhi + bo);
                        ldsm4(vl[h], sVlo + bo);
                    }
                    #pragma unroll
                    for (int nt = 0; nt < 4; ++nt) {
                        const uint32_t* vhp = &vh[nt >> 1][(nt & 1) * 2];
                        const uint32_t* vlp = &vl[nt >> 1][(nt & 1) * 2];
                        mma16816(o[nt], pa,  vhp);
                        mma16816(o[nt], pa,  vlp);
                        mma16816(o[nt], pal, vhp);
                    }
                }
            }
            __syncthreads();

            if (it + 2 < iters) {
                const int kn = (it + 2) * KT;
                const uint32_t kh_d = sb + AO_KHI + st * (KT * LDK * 2) + kr * (LDK * 2) + kq * 64;
                const uint32_t kl_d = sb + AO_KLO + st * (KT * LDK * 2) + kr * (LDK * 2) + kq * 64;
                const uint32_t vh_d = sb + AO_VHI + st * (HD * LDV * 2) + vr * (LDV * 2) + vhh * 64;
                const uint32_t vl_d = sb + AO_VLO + st * (HD * LDV * 2) + vr * (LDV * 2) + vhh * 64;
                const __nv_bfloat16* ksh = gKh + (size_t)(kn + kr) * HD + kq * 32;
                const __nv_bfloat16* ksl = gKl + (size_t)(kn + kr) * HD + kq * 32;
                const __nv_bfloat16* vsh = gVh + (size_t)vr * SEQ + kn + vhh * 32;
                const __nv_bfloat16* vsl = gVl + (size_t)vr * SEQ + kn + vhh * 32;
                #pragma unroll
                for (int j = 0; j < 4; ++j) {
                    cpa16(kh_d + j * 16, ksh + j * 8);
                    cpa16(kl_d + j * 16, ksl + j * 8);
                    cpa16(vh_d + j * 16, vsh + j * 8);
                    cpa16(vl_d + j * 16, vsl + j * 8);
                }
            }
            CP_COMMIT();
        }

        {
            const float li0 = 1.f / l_s[wm * 16 + g];
            const float li1 = 1.f / l_s[wm * 16 + g + 8];
            float* op0 = out + ((size_t)b * SEQ + q0 + wm * 16 + g) * HD;
            float* op1 = op0 + 8 * HD;
            #pragma unroll
            for (int nt = 0; nt < 4; ++nt) {
                const int d = wn * 32 + nt * 8 + tig * 2;
                *(float2*)(op0 + d) = make_float2(o[nt][0] * li0, o[nt][1] * li0);
                *(float2*)(op1 + d) = make_float2(o[nt][2] * li1, o[nt][3] * li1);
            }
        }
        __syncthreads();
    }
}

// ---------------------------------------------------------------------------
extern "C" void kernel_launch(void* const* d_in, const int* in_sizes, int n_in,
                              void* d_out, int out_size)
{
    const float* X  = (const float*)d_in[0];
    const float* Wq = (const float*)d_in[1];
    const float* bq = (const float*)d_in[2];
    const float* Wk = (const float*)d_in[3];
    const float* bk = (const float*)d_in[4];
    const float* Wv = (const float*)d_in[5];
    const float* bv = (const float*)d_in[6];
    float* out = (float*)d_out;

    prep3<<<1024, 256>>>(X, Wq, Wk, Wv);

    cudaFuncSetAttribute(qkv3, cudaFuncAttributeMaxDynamicSharedMemorySize,
                         QSM3_TOTAL);
    qkv3<<<dim3(128, 3), 256, QSM3_TOTAL>>>(bq, bk, bv);

    cudaFuncSetAttribute(attn4, cudaFuncAttributeMaxDynamicSharedMemorySize,
                         ASM_TOTAL);
    attn4<<<dim3(32, 4), 256, ASM_TOTAL>>>(out);
}